// round 15
// baseline (speedup 1.0000x reference)
#include <cuda_runtime.h>

#define FULL_MASK 0xffffffffu

__global__ void ord_zero_kernel(float* out) {
    if (threadIdx.x == 0 && blockIdx.x == 0) *out = 0.0f;
}

__device__ __forceinline__ float ex2f(float x) {
    float y; asm("ex2.approx.ftz.f32 %0, %1;" : "=f"(y) : "f"(x)); return y;
}
__device__ __forceinline__ float lg2f(float x) {
    float y; asm("lg2.approx.ftz.f32 %0, %1;" : "=f"(y) : "f"(x)); return y;
}

#define NEG_LOG2E (-1.4426950408889634f)

__device__ __forceinline__ float4 ldcs4(const float4* p) {
    return __ldcs(p);
}

// Process one row (v0,v1 = 8 contiguous elems per lane, t = target).
__device__ __forceinline__ void process_row(
    float4 v0, float4 v1, int t,
    int lane, bool last_lane,
    float& acc_r, float& acc_l2)
{
    // lane total via tree (short critical path into the scan)
    float t01 = v0.x + v0.y, t23 = v0.z + v0.w;
    float t45 = v1.x + v1.y, t67 = v1.z + v1.w;
    float tot = (t01 + t23) + (t45 + t67);

    // warp inclusive scan of lane totals
    float s = tot;
    #pragma unroll
    for (int o = 1; o < 32; o <<= 1) {
        float n = __shfl_up_sync(FULL_MASK, s, o);
        if (lane >= o) s += n;
    }
    const float cbase = s - tot;       // exclusive prefix for this lane
    const int   kt    = t - 8 * lane;  // i < kt  <=>  k < t

    // serial cumulative chain with cbase folded in
    float c0 = cbase + v0.x;
    float c1 = c0 + v0.y;
    float c2 = c1 + v0.z;
    float c3 = c2 + v0.w;
    float c4 = c3 + v1.x;
    float c5 = c4 + v1.y;
    float c6 = c5 + v1.z;
    float c7 = c6 + v1.w;

    float prod = 1.0f;
    float cl[8] = {c0, c1, c2, c3, c4, c5, c6, c7};

    #pragma unroll
    for (int i = 0; i < 8; ++i) {
        float c = cl[i];
        float u = (i < kt) ? c : -c;
        float e = ex2f(fabsf(c) * NEG_LOG2E);   // e^{-|c|}
        if (i == 7) {                            // exclude k == 255 (lane 31 only)
            u = last_lane ? -1.0f : u;
            e = last_lane ?  0.0f : e;
        }
        acc_r += fmaxf(u, 0.0f);
        prod   = fmaf(prod, e, prod);            // prod *= (1 + e)
    }
    acc_l2 += lg2f(prod);
}

// Warp-per-row, 8 contiguous elements per lane, depth-2 software pipeline,
// oversubscribed multi-wave grid (2048 CTAs).
__global__ __launch_bounds__(256, 5) void ord_loss_kernel(
    const float* __restrict__ logits,
    const long long* __restrict__ targets,
    float* __restrict__ out,
    int Btot)
{
    const int lane  = threadIdx.x & 31;
    const int wib   = threadIdx.x >> 5;
    const int gwarp = blockIdx.x * (blockDim.x >> 5) + wib;
    const int nwarp = gridDim.x * (blockDim.x >> 5);
    const bool last_lane = (lane == 31);

    float acc_r = 0.0f, acc_l2 = 0.0f;

    const float4* base4 = reinterpret_cast<const float4*>(logits);

    float4 x0, x1, y0, y1;
    int tx = 0, ty = 0;

    int row = gwarp;
    if (row < Btot) {
        const float4* rp = base4 + ((size_t)row << 6) + (lane << 1);
        x0 = ldcs4(rp);
        x1 = ldcs4(rp + 1);
        tx = (int)__ldcs(targets + row);
    }
    if (row + nwarp < Btot) {
        const float4* rp = base4 + ((size_t)(row + nwarp) << 6) + (lane << 1);
        y0 = ldcs4(rp);
        y1 = ldcs4(rp + 1);
        ty = (int)__ldcs(targets + (row + nwarp));
    }

    while (true) {
        // ---- X ----
        if (row >= Btot) break;
        {
            float4 v0 = x0, v1 = x1; int t = tx;
            const int pf = row + 2 * nwarp;
            if (pf < Btot) {
                const float4* rp = base4 + ((size_t)pf << 6) + (lane << 1);
                x0 = ldcs4(rp);
                x1 = ldcs4(rp + 1);
                tx = (int)__ldcs(targets + pf);
            }
            process_row(v0, v1, t, lane, last_lane, acc_r, acc_l2);
        }
        row += nwarp;

        // ---- Y ----
        if (row >= Btot) break;
        {
            float4 v0 = y0, v1 = y1; int t = ty;
            const int pf = row + 2 * nwarp;
            if (pf < Btot) {
                const float4* rp = base4 + ((size_t)pf << 6) + (lane << 1);
                y0 = ldcs4(rp);
                y1 = ldcs4(rp + 1);
                ty = (int)__ldcs(targets + pf);
            }
            process_row(v0, v1, t, lane, last_lane, acc_r, acc_l2);
        }
        row += nwarp;
    }

    float r = fmaf(0.69314718055994531f, acc_l2, acc_r);

    #pragma unroll
    for (int o = 16; o; o >>= 1) r += __shfl_xor_sync(FULL_MASK, r, o);

    __shared__ float ws[8];
    if (lane == 0) ws[wib] = r;
    __syncthreads();
    if (threadIdx.x == 0) {
        float ssum = 0.0f;
        #pragma unroll
        for (int i = 0; i < 8; ++i) ssum += ws[i];
        atomicAdd(out, ssum * (1.0f / (float)Btot));
    }
}

extern "C" void kernel_launch(void* const* d_in, const int* in_sizes, int n_in,
                              void* d_out, int out_size)
{
    const float*     logits  = (const float*)d_in[0];
    const long long* targets = (const long long*)d_in[1];
    float*           out     = (float*)d_out;

    const int B = in_sizes[1];

    ord_zero_kernel<<<1, 32>>>(out);
    ord_loss_kernel<<<2048, 256>>>(logits, targets, out, B);
}

// round 16
// speedup vs baseline: 1.0253x; 1.0253x over previous
#include <cuda_runtime.h>

#define FULL_MASK 0xffffffffu
#define GRID_CTAS 2048

__device__ __forceinline__ float ex2f(float x) {
    float y; asm("ex2.approx.ftz.f32 %0, %1;" : "=f"(y) : "f"(x)); return y;
}
__device__ __forceinline__ float lg2f(float x) {
    float y; asm("lg2.approx.ftz.f32 %0, %1;" : "=f"(y) : "f"(x)); return y;
}

__device__ float        g_partials[GRID_CTAS];
__device__ unsigned int g_ticket = 0;

// Warp-per-row, 8 contiguous elements per lane (fully coalesced LDG.128 x2),
// depth-2 software pipeline (two row buffers in flight). Body identical to the
// round-11 champion; finish is a single-kernel threadfence reduction.
__global__ __launch_bounds__(256, 5) void ord_loss_kernel(
    const float* __restrict__ logits,
    const long long* __restrict__ targets,
    float* __restrict__ out,
    int Btot)
{
    const int lane  = threadIdx.x & 31;
    const int wib   = threadIdx.x >> 5;
    const int gwarp = blockIdx.x * (blockDim.x >> 5) + wib;
    const int nwarp = gridDim.x * (blockDim.x >> 5);

    const bool last_lane = (lane == 31);
    const float NEG_LOG2E = -1.4426950408889634f;

    float acc_r = 0.0f, acc_l2 = 0.0f;

    const float4* base4 = reinterpret_cast<const float4*>(logits);

    float4 x0, x1, y0, y1;
    int tx = 0, ty = 0;

    int row = gwarp;
    if (row < Btot) {
        const float4* rp = base4 + (size_t)row * 64;
        x0 = rp[2 * lane];
        x1 = rp[2 * lane + 1];
        tx = *(const int*)(targets + row);
    }
    if (row + nwarp < Btot) {
        const float4* rp = base4 + (size_t)(row + nwarp) * 64;
        y0 = rp[2 * lane];
        y1 = rp[2 * lane + 1];
        ty = *(const int*)(targets + (row + nwarp));
    }

    while (true) {
        // ---- process X (row), prefetch row+2nw into X ----
        if (row >= Btot) break;
        {
            float p0 = x0.x;
            float p1 = p0 + x0.y;
            float p2 = p1 + x0.z;
            float p3 = p2 + x0.w;
            float p4 = p3 + x1.x;
            float p5 = p4 + x1.y;
            float p6 = p5 + x1.z;
            float p7 = p6 + x1.w;
            const int kt = tx - 8 * lane;

            const int pf = row + 2 * nwarp;
            if (pf < Btot) {
                const float4* rp = base4 + (size_t)pf * 64;
                x0 = rp[2 * lane];
                x1 = rp[2 * lane + 1];
                tx = *(const int*)(targets + pf);
            }

            float s = p7;
            #pragma unroll
            for (int o = 1; o < 32; o <<= 1) {
                float n = __shfl_up_sync(FULL_MASK, s, o);
                if (lane >= o) s += n;
            }
            const float cbase = s - p7;

            float prod = 1.0f;
            float pl[8] = {p0, p1, p2, p3, p4, p5, p6, p7};
            #pragma unroll
            for (int i = 0; i < 8; ++i) {
                float c = cbase + pl[i];
                float u = (i < kt) ? c : -c;
                float e = ex2f(fabsf(c) * NEG_LOG2E);
                if (i == 7) {
                    u = last_lane ? -1.0f : u;
                    e = last_lane ?  0.0f : e;
                }
                acc_r += fmaxf(u, 0.0f);
                prod   = fmaf(prod, e, prod);
            }
            acc_l2 += lg2f(prod);
        }
        row += nwarp;

        // ---- process Y (row), prefetch row+2nw into Y ----
        if (row >= Btot) break;
        {
            float p0 = y0.x;
            float p1 = p0 + y0.y;
            float p2 = p1 + y0.z;
            float p3 = p2 + y0.w;
            float p4 = p3 + y1.x;
            float p5 = p4 + y1.y;
            float p6 = p5 + y1.z;
            float p7 = p6 + y1.w;
            const int kt = ty - 8 * lane;

            const int pf = row + 2 * nwarp;
            if (pf < Btot) {
                const float4* rp = base4 + (size_t)pf * 64;
                y0 = rp[2 * lane];
                y1 = rp[2 * lane + 1];
                ty = *(const int*)(targets + pf);
            }

            float s = p7;
            #pragma unroll
            for (int o = 1; o < 32; o <<= 1) {
                float n = __shfl_up_sync(FULL_MASK, s, o);
                if (lane >= o) s += n;
            }
            const float cbase = s - p7;

            float prod = 1.0f;
            float pl[8] = {p0, p1, p2, p3, p4, p5, p6, p7};
            #pragma unroll
            for (int i = 0; i < 8; ++i) {
                float c = cbase + pl[i];
                float u = (i < kt) ? c : -c;
                float e = ex2f(fabsf(c) * NEG_LOG2E);
                if (i == 7) {
                    u = last_lane ? -1.0f : u;
                    e = last_lane ?  0.0f : e;
                }
                acc_r += fmaxf(u, 0.0f);
                prod   = fmaf(prod, e, prod);
            }
            acc_l2 += lg2f(prod);
        }
        row += nwarp;
    }

    float r = fmaf(0.69314718055994531f, acc_l2, acc_r);

    // intra-warp reduce
    #pragma unroll
    for (int o = 16; o; o >>= 1) r += __shfl_xor_sync(FULL_MASK, r, o);

    __shared__ float ws[8];
    __shared__ bool  is_last;
    if (lane == 0) ws[wib] = r;
    __syncthreads();

    if (threadIdx.x == 0) {
        float bsum = 0.0f;
        #pragma unroll
        for (int i = 0; i < 8; ++i) bsum += ws[i];
        g_partials[blockIdx.x] = bsum;
        __threadfence();
        unsigned int t = atomicAdd(&g_ticket, 1u);
        is_last = (t == (unsigned int)(gridDim.x - 1));
    }
    __syncthreads();

    // last block reduces all partials and writes the mean
    if (is_last) {
        float s = 0.0f;
        for (int i = threadIdx.x; i < GRID_CTAS; i += 256)
            s += g_partials[i];
        #pragma unroll
        for (int o = 16; o; o >>= 1) s += __shfl_xor_sync(FULL_MASK, s, o);
        if (lane == 0) ws[wib] = s;
        __syncthreads();
        if (threadIdx.x == 0) {
            float tot = 0.0f;
            #pragma unroll
            for (int i = 0; i < 8; ++i) tot += ws[i];
            *out = tot * (1.0f / (float)Btot);
            g_ticket = 0;            // reset for next graph replay
        }
    }
}

extern "C" void kernel_launch(void* const* d_in, const int* in_sizes, int n_in,
                              void* d_out, int out_size)
{
    const float*     logits  = (const float*)d_in[0];
    const long long* targets = (const long long*)d_in[1];
    float*           out     = (float*)d_out;

    const int B = in_sizes[1];

    ord_loss_kernel<<<GRID_CTAS, 256>>>(logits, targets, out, B);
}

// round 17
// speedup vs baseline: 1.0435x; 1.0178x over previous
#include <cuda_runtime.h>

#define FULL_MASK 0xffffffffu

__global__ void ord_zero_kernel(float* out) {
    if (threadIdx.x == 0 && blockIdx.x == 0) *out = 0.0f;
}

__device__ __forceinline__ float ex2f(float x) {
    float y; asm("ex2.approx.ftz.f32 %0, %1;" : "=f"(y) : "f"(x)); return y;
}
__device__ __forceinline__ float lg2f(float x) {
    float y; asm("lg2.approx.ftz.f32 %0, %1;" : "=f"(y) : "f"(x)); return y;
}

// Warp-per-row, 8 contiguous elements per lane (fully coalesced LDG.128 x2),
// depth-2 software pipeline (two row buffers in flight). Round-11 champion
// body, grid doubled to 4096 CTAs for faster CTA churn.
__global__ __launch_bounds__(256, 5) void ord_loss_kernel(
    const float* __restrict__ logits,
    const long long* __restrict__ targets,
    float* __restrict__ out,
    int Btot)
{
    const int lane  = threadIdx.x & 31;
    const int wib   = threadIdx.x >> 5;
    const int gwarp = blockIdx.x * (blockDim.x >> 5) + wib;
    const int nwarp = gridDim.x * (blockDim.x >> 5);

    const bool last_lane = (lane == 31);
    const float NEG_LOG2E = -1.4426950408889634f;

    float acc_r = 0.0f, acc_l2 = 0.0f;

    const float4* base4 = reinterpret_cast<const float4*>(logits);

    float4 x0, x1, y0, y1;
    int tx = 0, ty = 0;

    int row = gwarp;
    if (row < Btot) {
        const float4* rp = base4 + (size_t)row * 64;
        x0 = rp[2 * lane];
        x1 = rp[2 * lane + 1];
        tx = *(const int*)(targets + row);
    }
    if (row + nwarp < Btot) {
        const float4* rp = base4 + (size_t)(row + nwarp) * 64;
        y0 = rp[2 * lane];
        y1 = rp[2 * lane + 1];
        ty = *(const int*)(targets + (row + nwarp));
    }

    while (true) {
        // ---- process X (row), prefetch row+2nw into X ----
        if (row >= Btot) break;
        {
            float p0 = x0.x;
            float p1 = p0 + x0.y;
            float p2 = p1 + x0.z;
            float p3 = p2 + x0.w;
            float p4 = p3 + x1.x;
            float p5 = p4 + x1.y;
            float p6 = p5 + x1.z;
            float p7 = p6 + x1.w;
            const int kt = tx - 8 * lane;

            const int pf = row + 2 * nwarp;
            if (pf < Btot) {
                const float4* rp = base4 + (size_t)pf * 64;
                x0 = rp[2 * lane];
                x1 = rp[2 * lane + 1];
                tx = *(const int*)(targets + pf);
            }

            float s = p7;
            #pragma unroll
            for (int o = 1; o < 32; o <<= 1) {
                float n = __shfl_up_sync(FULL_MASK, s, o);
                if (lane >= o) s += n;
            }
            const float cbase = s - p7;

            float prod = 1.0f;
            float pl[8] = {p0, p1, p2, p3, p4, p5, p6, p7};
            #pragma unroll
            for (int i = 0; i < 8; ++i) {
                float c = cbase + pl[i];
                float u = (i < kt) ? c : -c;
                float e = ex2f(fabsf(c) * NEG_LOG2E);
                if (i == 7) {
                    u = last_lane ? -1.0f : u;
                    e = last_lane ?  0.0f : e;
                }
                acc_r += fmaxf(u, 0.0f);
                prod   = fmaf(prod, e, prod);
            }
            acc_l2 += lg2f(prod);
        }
        row += nwarp;

        // ---- process Y (row), prefetch row+2nw into Y ----
        if (row >= Btot) break;
        {
            float p0 = y0.x;
            float p1 = p0 + y0.y;
            float p2 = p1 + y0.z;
            float p3 = p2 + y0.w;
            float p4 = p3 + y1.x;
            float p5 = p4 + y1.y;
            float p6 = p5 + y1.z;
            float p7 = p6 + y1.w;
            const int kt = ty - 8 * lane;

            const int pf = row + 2 * nwarp;
            if (pf < Btot) {
                const float4* rp = base4 + (size_t)pf * 64;
                y0 = rp[2 * lane];
                y1 = rp[2 * lane + 1];
                ty = *(const int*)(targets + pf);
            }

            float s = p7;
            #pragma unroll
            for (int o = 1; o < 32; o <<= 1) {
                float n = __shfl_up_sync(FULL_MASK, s, o);
                if (lane >= o) s += n;
            }
            const float cbase = s - p7;

            float prod = 1.0f;
            float pl[8] = {p0, p1, p2, p3, p4, p5, p6, p7};
            #pragma unroll
            for (int i = 0; i < 8; ++i) {
                float c = cbase + pl[i];
                float u = (i < kt) ? c : -c;
                float e = ex2f(fabsf(c) * NEG_LOG2E);
                if (i == 7) {
                    u = last_lane ? -1.0f : u;
                    e = last_lane ?  0.0f : e;
                }
                acc_r += fmaxf(u, 0.0f);
                prod   = fmaf(prod, e, prod);
            }
            acc_l2 += lg2f(prod);
        }
        row += nwarp;
    }

    float r = fmaf(0.69314718055994531f, acc_l2, acc_r);

    #pragma unroll
    for (int o = 16; o; o >>= 1) r += __shfl_xor_sync(FULL_MASK, r, o);

    __shared__ float ws[8];
    if (lane == 0) ws[wib] = r;
    __syncthreads();
    if (threadIdx.x == 0) {
        float ssum = 0.0f;
        #pragma unroll
        for (int i = 0; i < 8; ++i) ssum += ws[i];
        atomicAdd(out, ssum * (1.0f / (float)Btot));
    }
}

extern "C" void kernel_launch(void* const* d_in, const int* in_sizes, int n_in,
                              void* d_out, int out_size)
{
    const float*     logits  = (const float*)d_in[0];
    const long long* targets = (const long long*)d_in[1];
    float*           out     = (float*)d_out;

    const int B = in_sizes[1];

    ord_zero_kernel<<<1, 32>>>(out);
    ord_loss_kernel<<<4096, 256>>>(logits, targets, out, B);
}